// round 4
// baseline (speedup 1.0000x reference)
#include <cuda_runtime.h>
#include <cstdint>

#define NEN   64368
#define NREL  12
#define DIM   128
#define NB    8
#define NITEM 6924
#define NE    1000000
#define BATCH 128
#define SEQL  32

#define ND4   (NEN * (DIM / 4))   // 2,059,776 float4 elements per (basis-slice / w-slice)

// ---------------- scratch (no cudaMalloc allowed) ----------------
__device__ __align__(16) float g_w[(size_t)NREL * NEN * DIM];    // 395 MB
__device__ __align__(16) float g_aggr[(size_t)NEN * DIM];        // 33 MB
__device__ __align__(16) float g_deg[NEN];
__device__ __align__(16) float g_nodes[(size_t)NEN * DIM];
__device__ __align__(16) float g_u[BATCH * DIM];

// ---------------- phase 0: zero accumulators ----------------
__global__ void k_zero() {
    int idx = blockIdx.x * blockDim.x + threadIdx.x;
    if (idx < ND4) ((float4*)g_aggr)[idx] = make_float4(0.f, 0.f, 0.f, 0.f);
    if (idx < NEN) g_deg[idx] = 0.f;
}

// ---------------- phase 1: w[r,n,d] = sum_b att[r,b] * basis[b,n,d] ----------------
__global__ void k_w(const float* __restrict__ basis, const float* __restrict__ att) {
    __shared__ float s_att[NREL * NB];
    int tid = threadIdx.x;
    if (tid < NREL * NB) s_att[tid] = att[tid];
    __syncthreads();

    int idx = blockIdx.x * blockDim.x + tid;   // over n*32 + d4
    if (idx >= ND4) return;

    const float4* b4 = (const float4*)basis;
    float4 bb[NB];
#pragma unroll
    for (int b = 0; b < NB; b++) bb[b] = __ldg(b4 + (size_t)b * ND4 + idx);

    float4* w4 = (float4*)g_w;
#pragma unroll
    for (int r = 0; r < NREL; r++) {
        float4 o = make_float4(0.f, 0.f, 0.f, 0.f);
#pragma unroll
        for (int b = 0; b < NB; b++) {
            float a = s_att[r * NB + b];
            o.x += a * bb[b].x;
            o.y += a * bb[b].y;
            o.z += a * bb[b].z;
            o.w += a * bb[b].w;
        }
        w4[(size_t)r * ND4 + idx] = o;
    }
}

// ---------------- phase 2: edge gather + scatter (1 warp per edge) ----------------
__global__ void k_edge(const int* __restrict__ ei, const int* __restrict__ et) {
    int gw   = (blockIdx.x * blockDim.x + threadIdx.x) >> 5;
    int lane = threadIdx.x & 31;
    if (gw >= NE) return;

    int src = __ldg(ei + gw);
    int dst = __ldg(ei + NE + gw);
    int t   = __ldg(et + gw);

    const float4* wrow = (const float4*)g_w + (size_t)(t * NEN + src) * (DIM / 4);
    float4 v = __ldg(wrow + lane);

    float* dp = g_aggr + (size_t)dst * DIM + lane * 4;
    asm volatile("red.global.add.v4.f32 [%0], {%1,%2,%3,%4};"
                 :: "l"(dp), "f"(v.x), "f"(v.y), "f"(v.z), "f"(v.w) : "memory");
    if (lane == 0)
        asm volatile("red.global.add.f32 [%0], %1;"
                     :: "l"(g_deg + dst), "f"(1.0f) : "memory");
}

// ---------------- phase 3: nodes = aggr/max(deg,1) + root + bias ----------------
__global__ void k_fin(const float* __restrict__ root, const float* __restrict__ bias) {
    int idx = blockIdx.x * blockDim.x + threadIdx.x;
    if (idx >= NEN * DIM) return;
    float d = g_deg[idx >> 7];
    g_nodes[idx] = g_aggr[idx] / fmaxf(d, 1.f) + root[idx] + bias[idx & 127];
}

// ---------------- phase 4: attention pooling (1 block per batch row) ----------------
__global__ void k_pool(const int* __restrict__ seed_ids, const int* __restrict__ seed_len,
                       const float* __restrict__ A, const float* __restrict__ bvec) {
    __shared__ float sh_h[SEQL][DIM];        // 16 KB
    __shared__ float sh_t[SEQL][DIM + 1];    // padded: conflict-free column reads
    __shared__ float sh_e[SEQL];
    __shared__ float sh_attn[SEQL];
    __shared__ int   sid[SEQL];

    int b = blockIdx.x;
    int j = threadIdx.x;      // 0..127
    int len = __ldg(seed_len + b);

    if (j < SEQL) sid[j] = __ldg(seed_ids + b * SEQL + j);
    __syncthreads();

#pragma unroll
    for (int l = 0; l < SEQL; l++)
        sh_h[l][j] = g_nodes[(size_t)sid[l] * DIM + j];
    __syncthreads();

    // pe[l] = sum_d h[l,d] * A[d,j]
    float pe[SEQL];
#pragma unroll
    for (int l = 0; l < SEQL; l++) pe[l] = 0.f;
    for (int d = 0; d < DIM; d++) {
        float a = __ldg(A + d * DIM + j);
#pragma unroll
        for (int l = 0; l < SEQL; l++) pe[l] += sh_h[l][d] * a;
    }
    float bv = __ldg(bvec + j);
#pragma unroll
    for (int l = 0; l < SEQL; l++) sh_t[l][j] = tanhf(pe[l]) * bv;
    __syncthreads();

    // e[l] = sum_j t[l,j]
    if (j < SEQL) {
        float s = 0.f;
        for (int d = 0; d < DIM; d++) s += sh_t[j][d];
        sh_e[j] = s;
    }
    __syncthreads();

    // masked softmax over first warp
    if (j < 32) {
        float val = (j < len) ? sh_e[j] : -1e30f;
        float m = val;
#pragma unroll
        for (int o = 16; o; o >>= 1) m = fmaxf(m, __shfl_xor_sync(0xffffffffu, m, o));
        float ex = (j < len) ? expf(val - m) : 0.f;
        float s = ex;
#pragma unroll
        for (int o = 16; o; o >>= 1) s += __shfl_xor_sync(0xffffffffu, s, o);
        sh_attn[j] = (len > 0) ? ex / s : 0.f;
    }
    __syncthreads();

    float u = 0.f;
#pragma unroll
    for (int l = 0; l < SEQL; l++) u += sh_attn[l] * sh_h[l][j];
    g_u[b * DIM + j] = u;
}

// ---------------- phase 5: scores = u @ nodes[:NITEM].T + out_bias ----------------
#define ITEMS 32
__global__ void k_score(const float* __restrict__ out_bias, float* __restrict__ out) {
    __shared__ float shn[ITEMS * DIM];         // 16 KB node tile
    __shared__ float shout[ITEMS][BATCH + 1];  // padded staging for coalesced stores

    int tid = threadIdx.x;   // 0..127, one thread per batch row b
    int i0  = blockIdx.x * ITEMS;

    for (int idx = tid; idx < ITEMS * DIM; idx += BATCH) {
        int it = idx >> 7, d = idx & 127;
        int item = i0 + it;
        shn[idx] = (item < NITEM) ? g_nodes[(size_t)item * DIM + d] : 0.f;
    }
    __syncthreads();

    float acc[ITEMS];
#pragma unroll
    for (int it = 0; it < ITEMS; it++) acc[it] = 0.f;

    const float4* u4   = (const float4*)(g_u + tid * DIM);
    const float4* shn4 = (const float4*)shn;
#pragma unroll 4
    for (int d4 = 0; d4 < DIM / 4; d4++) {
        float4 uv = u4[d4];
#pragma unroll
        for (int it = 0; it < ITEMS; it++) {
            float4 nv = shn4[it * (DIM / 4) + d4];   // broadcast LDS.128
            acc[it] += uv.x * nv.x + uv.y * nv.y + uv.z * nv.z + uv.w * nv.w;
        }
    }

#pragma unroll
    for (int it = 0; it < ITEMS; it++) shout[it][tid] = acc[it];
    __syncthreads();

    // coalesced stores: consecutive tid -> consecutive items
    for (int idx = tid; idx < BATCH * ITEMS; idx += BATCH) {
        int bb = idx >> 5, it = idx & 31;
        int item = i0 + it;
        if (item < NITEM)
            out[(size_t)bb * NITEM + item] = shout[it][bb] + __ldg(out_bias + item);
    }
}

// ---------------- launch ----------------
extern "C" void kernel_launch(void* const* d_in, const int* in_sizes, int n_in,
                              void* d_out, int out_size) {
    const int*   edge_idx  = (const int*)d_in[0];   // [2, E]
    const int*   edge_type = (const int*)d_in[1];   // [E]
    const int*   seed_ids  = (const int*)d_in[2];   // [B, L]
    const int*   seed_len  = (const int*)d_in[3];   // [B]
    // d_in[4] = labels (unused by reference output)
    const float* basis     = (const float*)d_in[5]; // [NB, N, D]
    const float* att       = (const float*)d_in[6]; // [R, NB]
    const float* root      = (const float*)d_in[7]; // [N, D]
    const float* rgcn_bias = (const float*)d_in[8]; // [D]
    const float* attn_a    = (const float*)d_in[9]; // [D, D]
    const float* attn_b    = (const float*)d_in[10];// [D, 1]
    const float* out_bias  = (const float*)d_in[11];// [NITEM]
    float* out = (float*)d_out;                     // [B, NITEM]

    k_zero <<<(ND4 + 255) / 256, 256>>>();
    k_w    <<<(ND4 + 255) / 256, 256>>>(basis, att);
    k_edge <<<(NE * 32) / 256, 256>>>(edge_idx, edge_type);
    k_fin  <<<(NEN * DIM + 255) / 256, 256>>>(root, rgcn_bias);
    k_pool <<<BATCH, DIM>>>(seed_ids, seed_len, attn_a, attn_b);
    k_score<<<(NITEM + ITEMS - 1) / ITEMS, BATCH>>>(out_bias, out);
}